// round 5
// baseline (speedup 1.0000x reference)
#include <cuda_runtime.h>

#define EPSF 1e-5f

typedef unsigned long long ull;

__device__ __forceinline__ ull pk2(float lo, float hi) {
    ull r; asm("mov.b64 %0, {%1,%2};" : "=l"(r) : "f"(lo), "f"(hi)); return r;
}
__device__ __forceinline__ ull fma2(ull a, ull b, ull c) {
    ull d; asm("fma.rn.f32x2 %0, %1, %2, %3;" : "=l"(d) : "l"(a), "l"(b), "l"(c)); return d;
}
__device__ __forceinline__ float2 up2(ull a) {
    float2 f; asm("mov.b64 {%0,%1}, %2;" : "=f"(f.x), "=f"(f.y) : "l"(a)); return f;
}

// Per-batch Gram partials (4 L-chunks x 136 triangular) and fused attn matrices.
__device__ float g_part[256 * 4 * 136];
__device__ float g_M[256 * 256];

// Row index for each triangular element e = c*(c+1)/2 + d, c in [0,16)
__constant__ unsigned char c_tri_row[136] = {
    0,
    1,1,
    2,2,2,
    3,3,3,3,
    4,4,4,4,4,
    5,5,5,5,5,5,
    6,6,6,6,6,6,6,
    7,7,7,7,7,7,7,7,
    8,8,8,8,8,8,8,8,8,
    9,9,9,9,9,9,9,9,9,9,
    10,10,10,10,10,10,10,10,10,10,10,
    11,11,11,11,11,11,11,11,11,11,11,11,
    12,12,12,12,12,12,12,12,12,12,12,12,12,
    13,13,13,13,13,13,13,13,13,13,13,13,13,13,
    14,14,14,14,14,14,14,14,14,14,14,14,14,14,14,
    15,15,15,15,15,15,15,15,15,15,15,15,15,15,15,15
};

// ---------------------------------------------------------------------------
// Kernel 1: per-batch Gram of c0, split into 4 L-chunks (blockIdx.x) for
// parallelism; explicit prefetch of next x values to hide DRAM latency.
// c0[c,l] = relu(sum_i w1e[c,i]*x[i,l] + s1[c])
// ---------------------------------------------------------------------------
__global__ __launch_bounds__(256, 1) void k_gram(
    const float* __restrict__ x, const float* __restrict__ wc1,
    const float* __restrict__ g1, const float* __restrict__ bt1,
    const float* __restrict__ m1, const float* __restrict__ v1)
{
    __shared__ float w1e[64];
    __shared__ float s1s[16];
    __shared__ float sred[8][136];

    const int tid   = threadIdx.x;
    const int chunk = blockIdx.x;
    const int b     = blockIdx.y;

    if (tid < 16) {
        float inv = g1[tid] * rsqrtf(v1[tid] + EPSF);
#pragma unroll
        for (int i = 0; i < 4; i++) w1e[tid * 4 + i] = wc1[tid * 4 + i] * inv;
        s1s[tid] = bt1[tid] - m1[tid] * inv;
    }
    __syncthreads();

    float acc[136];
#pragma unroll
    for (int e = 0; e < 136; e++) acc[e] = 0.f;

    const float* xb = x + (size_t)b * 4 * 8192 + chunk * 2048;

    float nx0 = xb[tid];
    float nx1 = xb[8192 + tid];
    float nx2 = xb[16384 + tid];
    float nx3 = xb[24576 + tid];

#pragma unroll 1
    for (int it = 0; it < 8; it++) {
        float xv0 = nx0, xv1 = nx1, xv2 = nx2, xv3 = nx3;
        if (it < 7) {
            int nl = tid + (it + 1) * 256;
            nx0 = xb[nl]; nx1 = xb[8192 + nl];
            nx2 = xb[16384 + nl]; nx3 = xb[24576 + nl];
        }
        float c0[16];
#pragma unroll
        for (int c = 0; c < 16; c++) {
            float4 w = *(const float4*)(w1e + c * 4);
            float v = fmaf(w.x, xv0, fmaf(w.y, xv1,
                      fmaf(w.z, xv2, fmaf(w.w, xv3, s1s[c]))));
            c0[c] = fmaxf(v, 0.f);
        }
        float* ap = acc;
#pragma unroll
        for (int c = 0; c < 16; c++) {
            float cc = c0[c];
#pragma unroll
            for (int d = 0; d <= c; d++)
                ap[d] = fmaf(cc, c0[d], ap[d]);
            ap += c + 1;
        }
    }

    const int lane = tid & 31;
    const int wrp  = tid >> 5;
#pragma unroll
    for (int e = 0; e < 136; e++) {
        float v = acc[e];
        v += __shfl_down_sync(0xffffffffu, v, 16);
        v += __shfl_down_sync(0xffffffffu, v, 8);
        v += __shfl_down_sync(0xffffffffu, v, 4);
        v += __shfl_down_sync(0xffffffffu, v, 2);
        v += __shfl_down_sync(0xffffffffu, v, 1);
        if (lane == 0) sred[wrp][e] = v;
    }
    __syncthreads();

    if (tid < 136) {
        float s = 0.f;
#pragma unroll
        for (int w2 = 0; w2 < 8; w2++) s += sred[w2][tid];
        g_part[(b * 4 + chunk) * 136 + tid] = s;
    }
}

// ---------------------------------------------------------------------------
// Kernel 2: sum partials, softmax, fold attn+wc2+beta+identity+BN2 into M.
// attn = softmax(rowmax(G)-G) == exp(rowmin-G)/sum
// M[c,d] = inv2[c]*(beta*sum_e wc2[c,e]*attn[e,d] + wc2[c,d])
// ---------------------------------------------------------------------------
__global__ void k_attn(
    const float* __restrict__ wc2, const float* __restrict__ g2,
    const float* __restrict__ bt2, const float* __restrict__ m2,
    const float* __restrict__ v2, const float* __restrict__ beta)
{
    __shared__ float gs[256];
    __shared__ float att[256];
    const int b = blockIdx.x;
    const int tid = threadIdx.x;

    for (int i = tid; i < 136; i += 32) {
        const float* p = g_part + b * 4 * 136 + i;
        float s = p[0] + p[136] + p[272] + p[408];
        int c = c_tri_row[i];
        int d = i - c * (c + 1) / 2;
        gs[c * 16 + d] = s;
        gs[d * 16 + c] = s;
    }
    __syncwarp();

    if (tid < 16) {
        float mn = gs[tid * 16];
#pragma unroll
        for (int d = 1; d < 16; d++) mn = fminf(mn, gs[tid * 16 + d]);
        float e[16];
        float s = 0.f;
#pragma unroll
        for (int d = 0; d < 16; d++) { e[d] = expf(mn - gs[tid * 16 + d]); s += e[d]; }
        float is = 1.f / s;
#pragma unroll
        for (int d = 0; d < 16; d++) att[tid * 16 + d] = e[d] * is;
    }
    __syncwarp();

    if (tid < 16) {
        float inv2 = g2[tid] * rsqrtf(v2[tid] + EPSF);
        float bv = beta[0];
#pragma unroll
        for (int d = 0; d < 16; d++) {
            float t = 0.f;
#pragma unroll
            for (int e2 = 0; e2 < 16; e2++)
                t = fmaf(wc2[tid * 16 + e2], att[e2 * 16 + d], t);
            g_M[b * 256 + tid * 16 + d] = inv2 * (bv * t + wc2[tid * 16 + d]);
        }
    }
}

// ---------------------------------------------------------------------------
// Kernel 3: fused main kernel. Tile T=512, 128 threads, 4 pos/thread.
// Inner products use packed fma.rn.f32x2 paired along the k (reduction) axis:
// weight pairs are contiguous LDS, accumulator lanes hold two partial sums,
// folded with one lo+hi add at the end.
// ---------------------------------------------------------------------------
constexpr int T3  = 512;
constexpr int XSZ = T3 + 64;   // 576: x tile, base = l0-32
constexpr int FSZ = T3 + 32;   // 544: fea0 tile, base = l0-16

__global__ __launch_bounds__(128) void k_main(
    const float* __restrict__ x,
    const float* __restrict__ w00, const float* __restrict__ b00,
    const float* __restrict__ w01, const float* __restrict__ b01,
    const float* __restrict__ w02, const float* __restrict__ b02,
    const float* __restrict__ wc1, const float* __restrict__ g1,
    const float* __restrict__ bt1, const float* __restrict__ m1,
    const float* __restrict__ v1,
    const float* __restrict__ g2, const float* __restrict__ bt2,
    const float* __restrict__ m2, const float* __restrict__ v2,
    float* __restrict__ out)
{
    __shared__ __align__(16) float xs[4 * XSZ];
    __shared__ __align__(16) float f0[8 * FSZ];
    __shared__ __align__(16) float w00s[1024];
    __shared__ __align__(16) float w01s[1024];
    __shared__ __align__(16) float w02s[1024];
    __shared__ __align__(16) float w1e[64];
    __shared__ __align__(16) float Ms[256];
    __shared__ float s1s[16], s2s[16], b00s[8], b01s[8], b02s[8];

    const int tid = threadIdx.x;
    const int b   = blockIdx.y;
    const int l0  = blockIdx.x * T3;

    // ---- stage weights / fused params ----
    for (int i = tid; i < 1024; i += 128) {
        w00s[i] = w00[i]; w01s[i] = w01[i]; w02s[i] = w02[i];
    }
    for (int i = tid; i < 256; i += 128) Ms[i] = g_M[b * 256 + i];
    if (tid < 16) {
        float inv = g1[tid] * rsqrtf(v1[tid] + EPSF);
#pragma unroll
        for (int i = 0; i < 4; i++) w1e[tid * 4 + i] = wc1[tid * 4 + i] * inv;
        s1s[tid] = bt1[tid] - m1[tid] * inv;
        float inv2 = g2[tid] * rsqrtf(v2[tid] + EPSF);
        s2s[tid] = bt2[tid] - m2[tid] * inv2;
        if (tid < 8) { b00s[tid] = b00[tid]; b01s[tid] = b01[tid]; b02s[tid] = b02[tid]; }
    }

    // ---- stage x tile (zero padded), base index l0-32 ----
    const float* xb = x + (size_t)b * 4 * 8192;
    for (int j = tid; j < 4 * XSZ; j += 128) {
        int i  = j / XSZ;
        int jj = j - i * XSZ;
        int gi = l0 - 32 + jj;
        xs[j] = (gi >= 0 && gi < 8192) ? xb[i * 8192 + gi] : 0.f;
    }
    __syncthreads();

    // ---- fea0 main part: 4 consecutive j per thread, all 8 out channels ----
    {
        const int jb = tid * 4;   // j in [0, 512)
        ull acc2[8][4];
#pragma unroll
        for (int o = 0; o < 8; o++)
#pragma unroll
            for (int p = 0; p < 4; p++) acc2[o][p] = 0ull;

#pragma unroll 1
        for (int i = 0; i < 4; i++) {
            float d0[36];
            const float4* xp = (const float4*)(xs + i * XSZ + jb);
#pragma unroll
            for (int j = 0; j < 9; j++) {
                float4 v = xp[j];
                d0[4*j] = v.x; d0[4*j+1] = v.y; d0[4*j+2] = v.z; d0[4*j+3] = v.w;
            }
            ull pr[35];
#pragma unroll
            for (int j = 0; j < 35; j++) pr[j] = pk2(d0[j], d0[j + 1]);
#pragma unroll
            for (int o = 0; o < 8; o++) {
                const ulonglong2* wq = (const ulonglong2*)(w00s + (o * 4 + i) * 32);
#pragma unroll
                for (int kq = 0; kq < 8; kq++) {
                    ulonglong2 wp = wq[kq];  // (w[4kq],w[4kq+1]) , (w[4kq+2],w[4kq+3])
#pragma unroll
                    for (int p = 0; p < 4; p++) {
                        acc2[o][p] = fma2(wp.x, pr[4 * kq + p],     acc2[o][p]);
                        acc2[o][p] = fma2(wp.y, pr[4 * kq + 2 + p], acc2[o][p]);
                    }
                }
            }
        }
        if (l0 == 0 && jb < 16) {
#pragma unroll
            for (int o = 0; o < 8; o++)
                *(float4*)(f0 + o * FSZ + jb) = make_float4(0.f, 0.f, 0.f, 0.f);
        } else {
#pragma unroll
            for (int o = 0; o < 8; o++) {
                float bo = b00s[o];
                float r[4];
#pragma unroll
                for (int p = 0; p < 4; p++) {
                    float2 u = up2(acc2[o][p]);
                    r[p] = u.x + u.y + bo;
                }
                *(float4*)(f0 + o * FSZ + jb) = make_float4(r[0], r[1], r[2], r[3]);
            }
        }
    }
    // ---- fea0 tail: j in [512, 544) by 32 threads ----
    if (tid < 32) {
        int j = 512 + tid;
        int t = l0 - 16 + j;
        float a8[8];
#pragma unroll
        for (int o = 0; o < 8; o++) a8[o] = 0.f;
#pragma unroll 1
        for (int i = 0; i < 4; i++)
#pragma unroll
            for (int kk = 0; kk < 32; kk++) {
                float xv = xs[i * XSZ + j + kk];
#pragma unroll
                for (int o = 0; o < 8; o++)
                    a8[o] = fmaf(xv, w00s[(o * 4 + i) * 32 + kk], a8[o]);
            }
#pragma unroll
        for (int o = 0; o < 8; o++)
            f0[o * FSZ + j] = (t <= 8192) ? a8[o] + b00s[o] : 0.f;
    }
    __syncthreads();

    // ---- output phase: 4 consecutive positions per thread ----
    const int lb = tid * 4;

    // fea1[o,l] = b01 + sum_{m,k} f0[m, lb+p+9+k] * w01[o,m,k]
    float r1[8][4];
    {
        ull a1[8][4];
#pragma unroll
        for (int o = 0; o < 8; o++)
#pragma unroll
            for (int p = 0; p < 4; p++) a1[o][p] = 0ull;

#pragma unroll 1
        for (int m = 0; m < 8; m++) {
            float d[20];   // f0 offsets lb+8 .. lb+27
            const float4* fp = (const float4*)(f0 + m * FSZ + lb + 8);
#pragma unroll
            for (int j = 0; j < 5; j++) {
                float4 v = fp[j];
                d[4*j] = v.x; d[4*j+1] = v.y; d[4*j+2] = v.z; d[4*j+3] = v.w;
            }
            ull pr[19];
#pragma unroll
            for (int j = 0; j < 19; j++) pr[j] = pk2(d[j], d[j + 1]);
#pragma unroll
            for (int o = 0; o < 8; o++) {
                const ulonglong2* wq = (const ulonglong2*)(w01s + (o * 8 + m) * 16);
#pragma unroll
                for (int kq = 0; kq < 4; kq++) {
                    ulonglong2 wp = wq[kq];
#pragma unroll
                    for (int p = 0; p < 4; p++) {
                        a1[o][p] = fma2(wp.x, pr[4 * kq + p + 1], a1[o][p]);
                        a1[o][p] = fma2(wp.y, pr[4 * kq + p + 3], a1[o][p]);
                    }
                }
            }
        }
#pragma unroll
        for (int o = 0; o < 8; o++)
#pragma unroll
            for (int p = 0; p < 4; p++) {
                float2 u = up2(a1[o][p]);
                r1[o][p] = u.x + u.y;
            }
    }

    // cf2[o,l] = b02 + sum_{m,k} f0[m, lb+p+2+2k] * w02[o,m,k]  (masked at edges)
    float r2[8][4];
    {
        ull a2[8][4];
#pragma unroll
        for (int o = 0; o < 8; o++)
#pragma unroll
            for (int p = 0; p < 4; p++) a2[o][p] = 0ull;

#pragma unroll 1
        for (int m = 0; m < 8; m++) {
            float d2[36];  // f0 offsets lb .. lb+35
            const float4* fp = (const float4*)(f0 + m * FSZ + lb);
#pragma unroll
            for (int j = 0; j < 9; j++) {
                float4 v = fp[j];
                d2[4*j] = v.x; d2[4*j+1] = v.y; d2[4*j+2] = v.z; d2[4*j+3] = v.w;
            }
            ull ps[32];    // ps[j] = (d2[j+2], d2[j+4]) : dilation-2 pairs
#pragma unroll
            for (int j = 0; j < 32; j++) ps[j] = pk2(d2[j + 2], d2[j + 4]);
#pragma unroll
            for (int o = 0; o < 8; o++) {
                const ulonglong2* wq = (const ulonglong2*)(w02s + (o * 8 + m) * 16);
#pragma unroll
                for (int kq = 0; kq < 4; kq++) {
                    ulonglong2 wp = wq[kq];
#pragma unroll
                    for (int p = 0; p < 4; p++) {
                        a2[o][p] = fma2(wp.x, ps[8 * kq + p],     a2[o][p]);
                        a2[o][p] = fma2(wp.y, ps[8 * kq + p + 4], a2[o][p]);
                    }
                }
            }
        }
#pragma unroll
        for (int o = 0; o < 8; o++)
#pragma unroll
            for (int p = 0; p < 4; p++) {
                float2 u = up2(a2[o][p]);
                r2[o][p] = u.x + u.y;
            }
    }

    // ---- channel-attention contribution: c2 = relu(M.c0 + s2) ----
    float xva[4][4];
#pragma unroll
    for (int i = 0; i < 4; i++) {
        float4 v = *(const float4*)(xs + i * XSZ + lb + 32);
        xva[i][0] = v.x; xva[i][1] = v.y; xva[i][2] = v.z; xva[i][3] = v.w;
    }
    ull xvp[2][4];
#pragma unroll
    for (int ih = 0; ih < 2; ih++)
#pragma unroll
        for (int p = 0; p < 4; p++)
            xvp[ih][p] = pk2(xva[2 * ih][p], xva[2 * ih + 1][p]);

    float c0a[16][4];
#pragma unroll
    for (int dch = 0; dch < 16; dch++) {
        const ull* wp = (const ull*)(w1e + dch * 4);
        ull w0 = wp[0], w1 = wp[1];
        float s = s1s[dch];
#pragma unroll
        for (int p = 0; p < 4; p++) {
            ull a = fma2(w0, xvp[0][p], fma2(w1, xvp[1][p], 0ull));
            float2 u = up2(a);
            c0a[dch][p] = fmaxf(u.x + u.y + s, 0.f);
        }
    }

    ull c0p[8][4];
#pragma unroll
    for (int dh = 0; dh < 8; dh++)
#pragma unroll
        for (int p = 0; p < 4; p++)
            c0p[dh][p] = pk2(c0a[2 * dh][p], c0a[2 * dh + 1][p]);

    float msk[4];
#pragma unroll
    for (int p = 0; p < 4; p++) {
        int l = l0 + lb + p;
        msk[p] = (l >= 1 && l < 8190) ? 1.f : 0.f;
    }

    float* ob = out + ((size_t)b * 16) * 8192 + l0 + lb;
#pragma unroll
    for (int c = 0; c < 16; c++) {
        const ulonglong2* mp = (const ulonglong2*)(Ms + c * 16);
        ull t2[4] = {0ull, 0ull, 0ull, 0ull};
#pragma unroll
        for (int q = 0; q < 4; q++) {
            ulonglong2 mm = mp[q];
#pragma unroll
            for (int p = 0; p < 4; p++) {
                t2[p] = fma2(mm.x, c0p[2 * q][p],     t2[p]);
                t2[p] = fma2(mm.y, c0p[2 * q + 1][p], t2[p]);
            }
        }
        float v[4];
#pragma unroll
        for (int p = 0; p < 4; p++) {
            float2 u = up2(t2[p]);
            float att = fmaxf(u.x + u.y + s2s[c], 0.f);
            float cf = (c < 8) ? (r1[c][p] + b01s[c])
                               : msk[p] * (r2[c - 8][p] + b02s[c - 8]);
            v[p] = cf + att;
        }
        *(float4*)(ob + c * 8192) = make_float4(v[0], v[1], v[2], v[3]);
    }
}

extern "C" void kernel_launch(void* const* d_in, const int* in_sizes, int n_in,
                              void* d_out, int out_size) {
    (void)in_sizes; (void)n_in; (void)out_size;
    const float* x    = (const float*)d_in[0];
    const float* w00  = (const float*)d_in[1];
    const float* b00  = (const float*)d_in[2];
    const float* w01  = (const float*)d_in[3];
    const float* b01  = (const float*)d_in[4];
    const float* w02  = (const float*)d_in[5];
    const float* b02  = (const float*)d_in[6];
    const float* wc1  = (const float*)d_in[7];
    const float* g1   = (const float*)d_in[8];
    const float* bt1  = (const float*)d_in[9];
    const float* m1   = (const float*)d_in[10];
    const float* v1   = (const float*)d_in[11];
    const float* beta = (const float*)d_in[12];
    const float* wc2  = (const float*)d_in[13];
    const float* g2   = (const float*)d_in[14];
    const float* bt2  = (const float*)d_in[15];
    const float* m2   = (const float*)d_in[16];
    const float* v2   = (const float*)d_in[17];
    float* out = (float*)d_out;

    k_gram<<<dim3(4, 256), 256>>>(x, wc1, g1, bt1, m1, v1);
    k_attn<<<256, 32>>>(wc2, g2, bt2, m2, v2, beta);
    k_main<<<dim3(8192 / T3, 256), 128>>>(
        x, w00, b00, w01, b01, w02, b02, wc1, g1, bt1, m1, v1,
        g2, bt2, m2, v2, out);
}

// round 7
// speedup vs baseline: 1.2393x; 1.2393x over previous
#include <cuda_runtime.h>

#define EPSF 1e-5f

// Per-batch 16x16 Gram matrices and fused channel-attention matrices.
__device__ float g_gram[256 * 256];
__device__ float g_M[256 * 256];

// Row index for each triangular element e = c*(c+1)/2 + d, c in [0,16)
__constant__ unsigned char c_tri_row[136] = {
    0,
    1,1,
    2,2,2,
    3,3,3,3,
    4,4,4,4,4,
    5,5,5,5,5,5,
    6,6,6,6,6,6,6,
    7,7,7,7,7,7,7,7,
    8,8,8,8,8,8,8,8,8,
    9,9,9,9,9,9,9,9,9,9,
    10,10,10,10,10,10,10,10,10,10,10,
    11,11,11,11,11,11,11,11,11,11,11,11,
    12,12,12,12,12,12,12,12,12,12,12,12,12,
    13,13,13,13,13,13,13,13,13,13,13,13,13,13,
    14,14,14,14,14,14,14,14,14,14,14,14,14,14,14,
    15,15,15,15,15,15,15,15,15,15,15,15,15,15,15,15
};

// ---------------------------------------------------------------------------
// Kernel 1: per-batch Gram of c0 (computed on the fly from x).
// c0[c,l] = relu(sum_i w1e[c,i]*x[i,l] + s1[c])
// float4 loads (4 positions/thread/iter) + 1-deep register double buffer:
// 64B/lane in flight instead of 16B -> latency-hiding via MLP, 8 iters total.
// ---------------------------------------------------------------------------
__global__ __launch_bounds__(256, 1) void k_gram(
    const float* __restrict__ x, const float* __restrict__ wc1,
    const float* __restrict__ g1, const float* __restrict__ bt1,
    const float* __restrict__ m1, const float* __restrict__ v1)
{
    __shared__ float w1e[64];
    __shared__ float s1s[16];
    __shared__ float sred[8][136];

    const int tid = threadIdx.x;
    const int b   = blockIdx.x;

    if (tid < 16) {
        float inv = g1[tid] * rsqrtf(v1[tid] + EPSF);
#pragma unroll
        for (int i = 0; i < 4; i++) w1e[tid * 4 + i] = wc1[tid * 4 + i] * inv;
        s1s[tid] = bt1[tid] - m1[tid] * inv;
    }
    __syncthreads();

    float acc[136];
#pragma unroll
    for (int e = 0; e < 136; e++) acc[e] = 0.f;

    const float* xb = x + (size_t)b * 4 * 8192;

    float4 nx[4];
#pragma unroll
    for (int ch = 0; ch < 4; ch++)
        nx[ch] = *(const float4*)(xb + ch * 8192 + tid * 4);

#pragma unroll 1
    for (int it = 0; it < 8; it++) {
        float cx[4][4];
#pragma unroll
        for (int ch = 0; ch < 4; ch++) {
            cx[ch][0] = nx[ch].x; cx[ch][1] = nx[ch].y;
            cx[ch][2] = nx[ch].z; cx[ch][3] = nx[ch].w;
        }
        if (it < 7) {
            int base = (it + 1) * 1024 + tid * 4;
#pragma unroll
            for (int ch = 0; ch < 4; ch++)
                nx[ch] = *(const float4*)(xb + ch * 8192 + base);
        }
#pragma unroll
        for (int p = 0; p < 4; p++) {
            float c0[16];
#pragma unroll
            for (int c = 0; c < 16; c++) {
                float4 w = *(const float4*)(w1e + c * 4);
                float v = fmaf(w.x, cx[0][p], fmaf(w.y, cx[1][p],
                          fmaf(w.z, cx[2][p], fmaf(w.w, cx[3][p], s1s[c]))));
                c0[c] = fmaxf(v, 0.f);
            }
            float* ap = acc;
#pragma unroll
            for (int c = 0; c < 16; c++) {
                float cc = c0[c];
#pragma unroll
                for (int d = 0; d <= c; d++)
                    ap[d] = fmaf(cc, c0[d], ap[d]);
                ap += c + 1;
            }
        }
    }

    const int lane = tid & 31;
    const int wrp  = tid >> 5;
#pragma unroll
    for (int e = 0; e < 136; e++) {
        float v = acc[e];
        v += __shfl_down_sync(0xffffffffu, v, 16);
        v += __shfl_down_sync(0xffffffffu, v, 8);
        v += __shfl_down_sync(0xffffffffu, v, 4);
        v += __shfl_down_sync(0xffffffffu, v, 2);
        v += __shfl_down_sync(0xffffffffu, v, 1);
        if (lane == 0) sred[wrp][e] = v;
    }
    __syncthreads();

    if (tid < 136) {
        float s = 0.f;
#pragma unroll
        for (int w2 = 0; w2 < 8; w2++) s += sred[w2][tid];
        int c = c_tri_row[tid];
        int d = tid - c * (c + 1) / 2;
        g_gram[b * 256 + c * 16 + d] = s;
        g_gram[b * 256 + d * 16 + c] = s;
    }
}

// ---------------------------------------------------------------------------
// Kernel 2: softmax + fold attention+wc2+beta+identity+BN2 into M (16x16/batch)
// attn = softmax(rowmax(G)-G) == exp(rowmin-G)/sum
// M[c,d] = inv2[c]*(beta*sum_e wc2[c,e]*attn[e,d] + wc2[c,d])
// ---------------------------------------------------------------------------
__global__ void k_attn(
    const float* __restrict__ wc2, const float* __restrict__ g2,
    const float* __restrict__ bt2, const float* __restrict__ m2,
    const float* __restrict__ v2, const float* __restrict__ beta)
{
    __shared__ float gs[256];
    __shared__ float att[256];
    const int b = blockIdx.x;
    const int tid = threadIdx.x;

    for (int i = tid; i < 256; i += 32) gs[i] = g_gram[b * 256 + i];
    __syncwarp();

    if (tid < 16) {
        float mn = gs[tid * 16];
#pragma unroll
        for (int d = 1; d < 16; d++) mn = fminf(mn, gs[tid * 16 + d]);
        float e[16];
        float s = 0.f;
#pragma unroll
        for (int d = 0; d < 16; d++) { e[d] = expf(mn - gs[tid * 16 + d]); s += e[d]; }
        float is = 1.f / s;
#pragma unroll
        for (int d = 0; d < 16; d++) att[tid * 16 + d] = e[d] * is;
    }
    __syncwarp();

    if (tid < 16) {
        float inv2 = g2[tid] * rsqrtf(v2[tid] + EPSF);
        float bv = beta[0];
#pragma unroll
        for (int d = 0; d < 16; d++) {
            float t = 0.f;
#pragma unroll
            for (int e2 = 0; e2 < 16; e2++)
                t = fmaf(wc2[tid * 16 + e2], att[e2 * 16 + d], t);
            g_M[b * 256 + tid * 16 + d] = inv2 * (bv * t + wc2[tid * 16 + d]);
        }
    }
}

// ---------------------------------------------------------------------------
// Kernel 3: fused main kernel. Tile T=512 positions, 128 threads, 4 pos/thread.
// (round-4 scalar-FFMA version: measured at the FFMA-issue roofline)
// ---------------------------------------------------------------------------
constexpr int T3  = 512;
constexpr int XSZ = T3 + 64;   // 576: x tile, base = l0-32
constexpr int FSZ = T3 + 32;   // 544: fea0 tile, base = l0-16 (index j -> t=l0-16+j)

__global__ __launch_bounds__(128) void k_main(
    const float* __restrict__ x,
    const float* __restrict__ w00, const float* __restrict__ b00,
    const float* __restrict__ w01, const float* __restrict__ b01,
    const float* __restrict__ w02, const float* __restrict__ b02,
    const float* __restrict__ wc1, const float* __restrict__ g1,
    const float* __restrict__ bt1, const float* __restrict__ m1,
    const float* __restrict__ v1,
    const float* __restrict__ g2, const float* __restrict__ bt2,
    const float* __restrict__ m2, const float* __restrict__ v2,
    float* __restrict__ out)
{
    __shared__ __align__(16) float xs[4 * XSZ];
    __shared__ __align__(16) float f0[8 * FSZ];
    __shared__ __align__(16) float w00s[1024];
    __shared__ __align__(16) float w01s[1024];
    __shared__ __align__(16) float w02s[1024];
    __shared__ __align__(16) float w1e[64];
    __shared__ __align__(16) float Ms[256];
    __shared__ float s1s[16], s2s[16], b00s[8], b01s[8], b02s[8];

    const int tid = threadIdx.x;
    const int b   = blockIdx.y;
    const int l0  = blockIdx.x * T3;

    // ---- stage weights / fused params ----
    for (int i = tid; i < 1024; i += 128) {
        w00s[i] = w00[i]; w01s[i] = w01[i]; w02s[i] = w02[i];
    }
    for (int i = tid; i < 256; i += 128) Ms[i] = g_M[b * 256 + i];
    if (tid < 16) {
        float inv = g1[tid] * rsqrtf(v1[tid] + EPSF);
#pragma unroll
        for (int i = 0; i < 4; i++) w1e[tid * 4 + i] = wc1[tid * 4 + i] * inv;
        s1s[tid] = bt1[tid] - m1[tid] * inv;
        float inv2 = g2[tid] * rsqrtf(v2[tid] + EPSF);
        s2s[tid] = bt2[tid] - m2[tid] * inv2;
        if (tid < 8) { b00s[tid] = b00[tid]; b01s[tid] = b01[tid]; b02s[tid] = b02[tid]; }
    }

    // ---- stage x tile (zero padded), base index l0-32 ----
    const float* xb = x + (size_t)b * 4 * 8192;
    for (int j = tid; j < 4 * XSZ; j += 128) {
        int i  = j / XSZ;
        int jj = j - i * XSZ;
        int gi = l0 - 32 + jj;
        xs[j] = (gi >= 0 && gi < 8192) ? xb[i * 8192 + gi] : 0.f;
    }
    __syncthreads();

    // ---- fea0 main part: 4 consecutive j per thread, all 8 out channels ----
    {
        const int jb = tid * 4;   // j in [0, 512)
        float acc[8][4];
#pragma unroll
        for (int o = 0; o < 8; o++)
#pragma unroll
            for (int p = 0; p < 4; p++) acc[o][p] = 0.f;

#pragma unroll 1
        for (int i = 0; i < 4; i++) {
            float d0[36];
            const float4* xp = (const float4*)(xs + i * XSZ + jb);
#pragma unroll
            for (int j = 0; j < 9; j++) {
                float4 v = xp[j];
                d0[4*j] = v.x; d0[4*j+1] = v.y; d0[4*j+2] = v.z; d0[4*j+3] = v.w;
            }
#pragma unroll
            for (int o = 0; o < 8; o++) {
                const float4* wq = (const float4*)(w00s + (o * 4 + i) * 32);
#pragma unroll
                for (int kq = 0; kq < 8; kq++) {
                    float4 w4 = wq[kq];
                    float wv[4] = { w4.x, w4.y, w4.z, w4.w };
#pragma unroll
                    for (int kk = 0; kk < 4; kk++) {
                        int k = kq * 4 + kk;
#pragma unroll
                        for (int p = 0; p < 4; p++)
                            acc[o][p] = fmaf(wv[kk], d0[k + p], acc[o][p]);
                    }
                }
            }
        }
        if (l0 == 0 && jb < 16) {
            // t = jb+p-16 < 0 for all four -> fea0 undefined region, zero
#pragma unroll
            for (int o = 0; o < 8; o++)
                *(float4*)(f0 + o * FSZ + jb) = make_float4(0.f, 0.f, 0.f, 0.f);
        } else {
#pragma unroll
            for (int o = 0; o < 8; o++) {
                float bo = b00s[o];
                *(float4*)(f0 + o * FSZ + jb) = make_float4(
                    acc[o][0] + bo, acc[o][1] + bo, acc[o][2] + bo, acc[o][3] + bo);
            }
        }
    }
    // ---- fea0 tail: j in [512, 544) by 32 threads ----
    if (tid < 32) {
        int j = 512 + tid;
        int t = l0 - 16 + j;
        float a8[8];
#pragma unroll
        for (int o = 0; o < 8; o++) a8[o] = 0.f;
#pragma unroll 1
        for (int i = 0; i < 4; i++)
#pragma unroll
            for (int kk = 0; kk < 32; kk++) {
                float xv = xs[i * XSZ + j + kk];
#pragma unroll
                for (int o = 0; o < 8; o++)
                    a8[o] = fmaf(xv, w00s[(o * 4 + i) * 32 + kk], a8[o]);
            }
#pragma unroll
        for (int o = 0; o < 8; o++)
            f0[o * FSZ + j] = (t <= 8192) ? a8[o] + b00s[o] : 0.f;
    }
    __syncthreads();

    // ---- output phase: 4 consecutive positions per thread ----
    const int lb = tid * 4;   // position relative to l0

    // fea1[o,l] = b01 + sum_{m,k} f0[m, lb+p+9+k] * w01[o,m,k]
    float r1[8][4];
#pragma unroll
    for (int o = 0; o < 8; o++)
#pragma unroll
        for (int p = 0; p < 4; p++) r1[o][p] = 0.f;

#pragma unroll 1
    for (int m = 0; m < 8; m++) {
        float d[20];   // f0 offsets lb+8 .. lb+27 ; needed lb+9+k+p -> d[k+p+1]
        const float4* fp = (const float4*)(f0 + m * FSZ + lb + 8);
#pragma unroll
        for (int j = 0; j < 5; j++) {
            float4 v = fp[j];
            d[4*j] = v.x; d[4*j+1] = v.y; d[4*j+2] = v.z; d[4*j+3] = v.w;
        }
#pragma unroll
        for (int o = 0; o < 8; o++) {
            const float4* wq = (const float4*)(w01s + (o * 8 + m) * 16);
#pragma unroll
            for (int kq = 0; kq < 4; kq++) {
                float4 w4 = wq[kq];
                float wv[4] = { w4.x, w4.y, w4.z, w4.w };
#pragma unroll
                for (int kk = 0; kk < 4; kk++) {
                    int k = kq * 4 + kk;
#pragma unroll
                    for (int p = 0; p < 4; p++)
                        r1[o][p] = fmaf(wv[kk], d[k + p + 1], r1[o][p]);
                }
            }
        }
    }

    // cf2[o,l] = b02 + sum_{m,k} f0[m, lb+p+2+2k] * w02[o,m,k]  (masked at edges)
    float r2[8][4];
#pragma unroll
    for (int o = 0; o < 8; o++)
#pragma unroll
        for (int p = 0; p < 4; p++) r2[o][p] = 0.f;

#pragma unroll 1
    for (int m = 0; m < 8; m++) {
        float d2[36];  // f0 offsets lb .. lb+35 ; needed lb+2+2k+p -> d2[2+2k+p]
        const float4* fp = (const float4*)(f0 + m * FSZ + lb);
#pragma unroll
        for (int j = 0; j < 9; j++) {
            float4 v = fp[j];
            d2[4*j] = v.x; d2[4*j+1] = v.y; d2[4*j+2] = v.z; d2[4*j+3] = v.w;
        }
#pragma unroll
        for (int o = 0; o < 8; o++) {
            const float4* wq = (const float4*)(w02s + (o * 8 + m) * 16);
#pragma unroll
            for (int kq = 0; kq < 4; kq++) {
                float4 w4 = wq[kq];
                float wv[4] = { w4.x, w4.y, w4.z, w4.w };
#pragma unroll
                for (int kk = 0; kk < 4; kk++) {
                    int k = kq * 4 + kk;
#pragma unroll
                    for (int p = 0; p < 4; p++)
                        r2[o][p] = fmaf(wv[kk], d2[2 * k + p + 2], r2[o][p]);
                }
            }
        }
    }

    // ---- channel-attention contribution: c2 = relu(M.c0 + s2) ----
    float xva[4][4];
#pragma unroll
    for (int i = 0; i < 4; i++) {
        float4 v = *(const float4*)(xs + i * XSZ + lb + 32);
        xva[i][0] = v.x; xva[i][1] = v.y; xva[i][2] = v.z; xva[i][3] = v.w;
    }
    float c0a[16][4];
#pragma unroll
    for (int dch = 0; dch < 16; dch++) {
        float4 w = *(const float4*)(w1e + dch * 4);
        float s = s1s[dch];
#pragma unroll
        for (int p = 0; p < 4; p++) {
            float v = fmaf(w.x, xva[0][p], fmaf(w.y, xva[1][p],
                      fmaf(w.z, xva[2][p], fmaf(w.w, xva[3][p], s))));
            c0a[dch][p] = fmaxf(v, 0.f);
        }
    }

    float msk[4];
#pragma unroll
    for (int p = 0; p < 4; p++) {
        int l = l0 + lb + p;
        msk[p] = (l >= 1 && l < 8190) ? 1.f : 0.f;
    }

    float* ob = out + ((size_t)b * 16) * 8192 + l0 + lb;
#pragma unroll
    for (int c = 0; c < 16; c++) {
        float t[4];
#pragma unroll
        for (int p = 0; p < 4; p++) t[p] = s2s[c];
#pragma unroll
        for (int dch = 0; dch < 16; dch += 4) {
            float4 mm = *(const float4*)(Ms + c * 16 + dch);
#pragma unroll
            for (int p = 0; p < 4; p++) {
                t[p] = fmaf(mm.x, c0a[dch][p], t[p]);
                t[p] = fmaf(mm.y, c0a[dch + 1][p], t[p]);
                t[p] = fmaf(mm.z, c0a[dch + 2][p], t[p]);
                t[p] = fmaf(mm.w, c0a[dch + 3][p], t[p]);
            }
        }
        float v[4];
#pragma unroll
        for (int p = 0; p < 4; p++) {
            float cf = (c < 8) ? (r1[c][p] + b01s[c])
                               : msk[p] * (r2[c - 8][p] + b02s[c - 8]);
            v[p] = cf + fmaxf(t[p], 0.f);
        }
        *(float4*)(ob + c * 8192) = make_float4(v[0], v[1], v[2], v[3]);
    }
}

extern "C" void kernel_launch(void* const* d_in, const int* in_sizes, int n_in,
                              void* d_out, int out_size) {
    (void)in_sizes; (void)n_in; (void)out_size;
    const float* x    = (const float*)d_in[0];
    const float* w00  = (const float*)d_in[1];
    const float* b00  = (const float*)d_in[2];
    const float* w01  = (const float*)d_in[3];
    const float* b01  = (const float*)d_in[4];
    const float* w02  = (const float*)d_in[5];
    const float* b02  = (const float*)d_in[6];
    const float* wc1  = (const float*)d_in[7];
    const float* g1   = (const float*)d_in[8];
    const float* bt1  = (const float*)d_in[9];
    const float* m1   = (const float*)d_in[10];
    const float* v1   = (const float*)d_in[11];
    const float* beta = (const float*)d_in[12];
    const float* wc2  = (const float*)d_in[13];
    const float* g2   = (const float*)d_in[14];
    const float* bt2  = (const float*)d_in[15];
    const float* m2   = (const float*)d_in[16];
    const float* v2   = (const float*)d_in[17];
    float* out = (float*)d_out;

    k_gram<<<256, 256>>>(x, wc1, g1, bt1, m1, v1);
    k_attn<<<256, 32>>>(wc2, g2, bt2, m2, v2, beta);
    k_main<<<dim3(8192 / T3, 256), 128>>>(
        x, w00, b00, w01, b01, w02, b02, wc1, g1, bt1, m1, v1,
        g2, bt2, m2, v2, out);
}